// round 17
// baseline (speedup 1.0000x reference)
#include <cuda_runtime.h>
#include <cuda_fp16.h>
#include <cstdint>

#define B_ 8
#define N_ 1024
#define C_ 768
#define H_ 12
#define HD 64
#define M_TOT (B_*N_)
#define QKV_N (3*C_)
#define EPS 1e-6f
#define EPSN (1e-6f/1024.0f)
#define SC2E 0.18033688011112042f
#define SWZ(b) ((b) ^ (((b) >> 3) & 0x70))

__device__ __forceinline__ uint32_t smem_to_u32(const void* p) {
    uint32_t a;
    asm("{ .reg .u64 t; cvta.to.shared.u64 t, %1; cvt.u32.u64 %0, t; }" : "=r"(a) : "l"(p));
    return a;
}
__device__ __forceinline__ void cpa16(uint32_t dst, const void* src) {
    asm volatile("cp.async.cg.shared.global [%0], [%1], 16;" :: "r"(dst), "l"(src));
}
#define CP_COMMIT() asm volatile("cp.async.commit_group;" ::: "memory")
#define CP_WAIT1()  asm volatile("cp.async.wait_group 1;" ::: "memory")
#define CP_WAIT2()  asm volatile("cp.async.wait_group 2;" ::: "memory")
#define LDM4(r, a) \
    asm volatile("ldmatrix.sync.aligned.m8n8.x4.shared.b16 {%0,%1,%2,%3}, [%4];" \
        : "=r"((r)[0]), "=r"((r)[1]), "=r"((r)[2]), "=r"((r)[3]) : "r"(a))
#define LDM4T(r, a) \
    asm volatile("ldmatrix.sync.aligned.m8n8.x4.trans.shared.b16 {%0,%1,%2,%3}, [%4];" \
        : "=r"((r)[0]), "=r"((r)[1]), "=r"((r)[2]), "=r"((r)[3]) : "r"(a))
#define MMAH(d, a, b0, b1) \
    asm volatile("mma.sync.aligned.m16n8k16.row.col.f32.f16.f16.f32 " \
        "{%0,%1,%2,%3}, {%4,%5,%6,%7}, {%8,%9}, {%0,%1,%2,%3};" \
        : "+f"((d)[0]), "+f"((d)[1]), "+f"((d)[2]), "+f"((d)[3]) \
        : "r"((a)[0]), "r"((a)[1]), "r"((a)[2]), "r"((a)[3]), "r"(b0), "r"(b1))

__device__ __forceinline__ uint32_t pack2h(float e0, float e1) {
    uint32_t r;
    asm("cvt.rn.f16x2.f32 %0, %1, %2;" : "=r"(r) : "f"(e1), "f"(e0));
    return r;
}
__device__ __forceinline__ float ex2(float x) {
    float y; asm("ex2.approx.f32 %0, %1;" : "=f"(y) : "f"(x)); return y;
}
__device__ __forceinline__ uint32_t ex2h2(uint32_t x) {
    uint32_t y; asm("ex2.approx.f16x2 %0, %1;" : "=r"(y) : "r"(x)); return y;
}
__device__ __forceinline__ uint32_t hmul2(uint32_t a, uint32_t b) {
    uint32_t y; asm("mul.f16x2 %0, %1, %2;" : "=r"(y) : "r"(a), "r"(b)); return y;
}

// --------------------------- scratch ---------------------------------------
__device__ __half g_xh[M_TOT*C_];
__device__ __half g_wqh[QKV_N*C_];
__device__ __half g_wph[C_*C_];
__device__ __half g_polh[B_*N_];
__device__ __half g_qh[B_*H_*N_*HD];
__device__ __half g_kh[B_*H_*N_*HD];
__device__ __half g_vh[B_*H_*N_*HD];
__device__ __half g_ah[M_TOT*C_];
__device__ float g_vsum[B_*H_*HD];

// -------- fused fp32 -> fp16 quant (x | Wqkv | Wproj | policy) --------------
#define NX4  (M_TOT*C_/4)
#define NWQ4 (QKV_N*C_/4)
#define NWP4 (C_*C_/4)
#define NP4  (B_*N_/4)
__global__ __launch_bounds__(256) void quant_all_kernel(const float* __restrict__ x,
                                                        const float* __restrict__ wq,
                                                        const float* __restrict__ wp,
                                                        const float* __restrict__ pol) {
    int i = blockIdx.x * 256 + threadIdx.x;
    const float* in; __half* outp; int j = i;
    if (j < NX4) { in = x; outp = g_xh; }
    else if ((j -= NX4) < NWQ4) { in = wq; outp = g_wqh; }
    else if ((j -= NWQ4) < NWP4) { in = wp; outp = g_wph; }
    else if ((j -= NWP4) < NP4) { in = pol; outp = g_polh; }
    else return;
    float4 v = ((const float4*)in)[j];
    ((uint32_t*)outp)[2*j]   = pack2h(v.x, v.y);
    ((uint32_t*)outp)[2*j+1] = pack2h(v.z, v.w);
}

// --------------- fp16 tensor-core GEMM, 128x128 tile (qkv) ------------------
#define GST 32768
__device__ __forceinline__ void load_chunk(uint32_t sb,
    const __half* __restrict__ Ah, const __half* __restrict__ Bh,
    int bm, int bn, int kc, int tid)
{
    const int g = tid & 7;
    const int rb = tid >> 3;
    const int koff = kc * 64 + g * 8;
    #pragma unroll
    for (int i = 0; i < 4; i++) {
        const int r = rb + 32 * i;
        const uint32_t d = SWZ((uint32_t)(r * 128 + g * 16));
        cpa16(sb + 0*16384 + d, Ah + (size_t)(bm + r) * C_ + koff);
        cpa16(sb + 1*16384 + d, Bh + (size_t)(bn + r) * C_ + koff);
    }
}

__global__ __launch_bounds__(256, 2) void mma_gemm_kernel(
    const __half* __restrict__ Ah, const __half* __restrict__ Bh)
{
    extern __shared__ char dsmem[];
    const int tid = threadIdx.x, wid = tid >> 5, lane = tid & 31;
    const int wm = wid >> 2, wn = wid & 3;
    const uint32_t sb0 = (smem_to_u32(dsmem) + 1023u) & ~1023u;

    const int bm = blockIdx.y * 128, bn = blockIdx.x * 128;
    const int lrow = (lane & 7) + ((lane >> 3) & 1) * 8;
    const int lkb  = (lane >> 4) * 16;

    float acc[4][4][4] = {};

    load_chunk(sb0,         Ah, Bh, bm, bn, 0, tid); CP_COMMIT();
    load_chunk(sb0 + GST,   Ah, Bh, bm, bn, 1, tid); CP_COMMIT();
    load_chunk(sb0 + 2*GST, Ah, Bh, bm, bn, 2, tid); CP_COMMIT();

    int sidx = 0;
    for (int i = 0; i < 12; i++) {
        CP_WAIT2();
        __syncthreads();
        const uint32_t sb = sb0 + sidx * GST;
        #pragma unroll
        for (int ks = 0; ks < 4; ks++) {
            uint32_t ah[4][4];
            #pragma unroll
            for (int mi = 0; mi < 4; mi++) {
                const uint32_t off =
                    SWZ((uint32_t)((wm*64 + mi*16 + lrow) * 128 + ks*32 + lkb));
                LDM4(ah[mi], sb + 0*16384 + off);
            }
            uint32_t bh[2][4];
            #pragma unroll
            for (int nb = 0; nb < 2; nb++) {
                const uint32_t off =
                    SWZ((uint32_t)((wn*32 + nb*16 + lrow) * 128 + ks*32 + lkb));
                LDM4(bh[nb], sb + 1*16384 + off);
            }
            #pragma unroll
            for (int mi = 0; mi < 4; mi++)
                #pragma unroll
                for (int ni = 0; ni < 4; ni++) {
                    const int nb = ni >> 1, hl = ni & 1;
                    MMAH(acc[mi][ni], ah[mi], bh[nb][hl], bh[nb][2+hl]);
                }
        }
        __syncthreads();
        if (i + 3 < 12) load_chunk(sb, Ah, Bh, bm, bn, i + 3, tid);
        CP_COMMIT();
        sidx = (sidx == 2) ? 0 : sidx + 1;
    }

    const int g = lane >> 2, c2 = (lane & 3) * 2;
    #pragma unroll
    for (int mi = 0; mi < 4; mi++)
        #pragma unroll
        for (int ni = 0; ni < 4; ni++) {
            const int col = bn + wn*32 + ni*8 + c2;
            #pragma unroll
            for (int half = 0; half < 2; half++) {
                const int m = bm + wm*64 + mi*16 + g + half*8;
                float d0 = acc[mi][ni][half*2], d1 = acc[mi][ni][half*2+1];
                const int which = col / C_;
                const int rest = col - which * C_;
                const int h = rest >> 6, dd = rest & 63;
                const int b = m >> 10, tok = m & 1023;
                const size_t idx = (((size_t)(b * H_ + h) * N_ + tok) * HD + dd) >> 1;
                if (which == 0) {
                    ((uint32_t*)g_qh)[idx] = pack2h(d0 * SC2E, d1 * SC2E);
                } else if (which == 1) {
                    ((uint32_t*)g_kh)[idx] = pack2h(d0, d1);
                } else {
                    ((uint32_t*)g_vh)[idx] = pack2h(d0, d1);
                }
            }
        }
}

// --------------- fp16 tensor-core GEMM, 128x64 tile (proj) ------------------
#define GST64 24576
__device__ __forceinline__ void load_chunk64(uint32_t sb,
    const __half* __restrict__ Ah, const __half* __restrict__ Bh,
    int bm, int bn, int kc, int tid)
{
    const int g = tid & 7;
    const int rb = tid >> 3;
    const int koff = kc * 64 + g * 8;
    #pragma unroll
    for (int i = 0; i < 4; i++) {
        const int r = rb + 32 * i;
        const uint32_t d = SWZ((uint32_t)(r * 128 + g * 16));
        cpa16(sb + d, Ah + (size_t)(bm + r) * C_ + koff);
    }
    #pragma unroll
    for (int i = 0; i < 2; i++) {
        const int r = rb + 32 * i;
        const uint32_t d = SWZ((uint32_t)(r * 128 + g * 16));
        cpa16(sb + 16384 + d, Bh + (size_t)(bn + r) * C_ + koff);
    }
}

__global__ __launch_bounds__(256, 3) void mma_gemm64_kernel(
    const __half* __restrict__ Ah, const __half* __restrict__ Bh,
    const float* __restrict__ bias, float* __restrict__ outp)
{
    extern __shared__ char dsmem[];
    const int tid = threadIdx.x, wid = tid >> 5, lane = tid & 31;
    const int wm = wid >> 1, wn = wid & 1;        // warp tile 32m x 32n
    const uint32_t sb0 = (smem_to_u32(dsmem) + 1023u) & ~1023u;

    const int bm = blockIdx.y * 128, bn = blockIdx.x * 64;
    const int lrow = (lane & 7) + ((lane >> 3) & 1) * 8;
    const int lkb  = (lane >> 4) * 16;

    float acc[2][4][4] = {};

    load_chunk64(sb0,         Ah, Bh, bm, bn, 0, tid); CP_COMMIT();
    load_chunk64(sb0 + GST64, Ah, Bh, bm, bn, 1, tid); CP_COMMIT();

    for (int i = 0; i < 12; i++) {
        CP_WAIT1();
        __syncthreads();
        const uint32_t sb = sb0 + (i & 1) * GST64;
        #pragma unroll
        for (int ks = 0; ks < 4; ks++) {
            uint32_t ah[2][4];
            #pragma unroll
            for (int mi = 0; mi < 2; mi++) {
                const uint32_t off =
                    SWZ((uint32_t)((wm*32 + mi*16 + lrow) * 128 + ks*32 + lkb));
                LDM4(ah[mi], sb + off);
            }
            uint32_t bh[2][4];
            #pragma unroll
            for (int nb = 0; nb < 2; nb++) {
                const uint32_t off =
                    SWZ((uint32_t)((wn*32 + nb*16 + lrow) * 128 + ks*32 + lkb));
                LDM4(bh[nb], sb + 16384 + off);
            }
            #pragma unroll
            for (int mi = 0; mi < 2; mi++)
                #pragma unroll
                for (int ni = 0; ni < 4; ni++) {
                    const int nb = ni >> 1, hl = ni & 1;
                    MMAH(acc[mi][ni], ah[mi], bh[nb][hl], bh[nb][2+hl]);
                }
        }
        __syncthreads();
        if (i + 2 < 12) load_chunk64(sb, Ah, Bh, bm, bn, i + 2, tid);
        CP_COMMIT();
    }

    const int g = lane >> 2, c2 = (lane & 3) * 2;
    #pragma unroll
    for (int mi = 0; mi < 2; mi++)
        #pragma unroll
        for (int ni = 0; ni < 4; ni++) {
            const int col = bn + wn*32 + ni*8 + c2;
            #pragma unroll
            for (int half = 0; half < 2; half++) {
                const int m = bm + wm*32 + mi*16 + g + half*8;
                float* p = outp + (size_t)m * C_ + col;
                p[0] = acc[mi][ni][half*2]   + bias[col];
                p[1] = acc[mi][ni][half*2+1] + bias[col + 1];
            }
        }
}

// --------------------- V row-sum per (b,h) ----------------------------------
__global__ __launch_bounds__(256) void vsum_kernel() {
    const int bh = blockIdx.x;
    const int wid = threadIdx.x >> 5, lane = threadIdx.x & 31;
    __shared__ float sm[8][64];
    float a0 = 0.f, a1 = 0.f;
    for (int n = wid * 128; n < wid * 128 + 128; n++) {
        const size_t idx = (((size_t)bh * N_ + n) * HD >> 1) + lane;
        uint32_t hv = ((const uint32_t*)g_vh)[idx];
        __half2 h = *reinterpret_cast<__half2*>(&hv);
        a0 += __low2float(h);
        a1 += __high2float(h);
    }
    sm[wid][lane*2] = a0; sm[wid][lane*2+1] = a1;
    __syncthreads();
    if (threadIdx.x < 64) {
        float s = 0.f;
        #pragma unroll
        for (int w = 0; w < 8; w++) s += sm[w][threadIdx.x];
        g_vsum[bh * HD + threadIdx.x] = s;
    }
}

// ------------------ tensor-core flash attention -----------------------------
// Fixed-base softmax; base folded into the S accumulator init (Sf starts at
// -mb), so no per-element subtraction after tile 0.
#define AST 32768
__global__ __launch_bounds__(256, 2) void attn_mma_kernel(const float* __restrict__ policy) {
    extern __shared__ char dsmem[];
    const uint32_t dbase = smem_to_u32(dsmem);
    const uint32_t sb0 = (dbase + 1023u) & ~1023u;
    char* sbp = dsmem + (sb0 - dbase);

    const int qt = blockIdx.x;
    const int bh = blockIdx.y;
    const int b  = bh / H_;
    const int h  = bh - b * H_;
    const int tid = threadIdx.x, w = tid >> 5, lane = tid & 31;
    const int lrow = (lane & 7) + ((lane >> 3) & 1) * 8;
    const int lkb  = (lane >> 4) * 16;
    const int c2   = (lane & 3) * 2;
    const int r0   = lane >> 2;

    const uint32_t QH = sb0;
    const uint32_t ST0 = sb0 + 16384;
    const uint32_t PK0 = sb0 + 16384 + 2*AST;

    const int g8 = tid & 7, rb = tid >> 3;
    const size_t bhN = (size_t)bh * N_;
    const uint32_t ONESH = 0x3C003C00u;

    #pragma unroll
    for (int i = 0; i < 4; i++) {
        const int r = rb + 32 * i;
        const uint32_t d = SWZ((uint32_t)(r * 128 + g8 * 16));
        cpa16(QH + d, g_qh + (bhN + qt * 128 + r) * HD + g8 * 8);
        const size_t src = (bhN + r) * HD + g8 * 8;
        cpa16(ST0 + 0*16384 + d, g_kh + src);
        cpa16(ST0 + 1*16384 + d, g_vh + src);
    }
    if (tid < 16) cpa16(PK0 + tid * 16, g_polh + b * N_ + tid * 8);
    CP_COMMIT();
    #pragma unroll
    for (int i = 0; i < 4; i++) {
        const int r = rb + 32 * i;
        const uint32_t d = SWZ((uint32_t)(r * 128 + g8 * 16));
        const size_t src = (bhN + 128 + r) * HD + g8 * 8;
        cpa16(ST0 + AST + 0*16384 + d, g_kh + src);
        cpa16(ST0 + AST + 1*16384 + d, g_vh + src);
    }
    if (tid < 16) cpa16(PK0 + 256 + tid * 16, g_polh + b * N_ + 128 + tid * 8);
    CP_COMMIT();
    CP_WAIT1();
    __syncthreads();

    uint32_t qh[4][4];
    #pragma unroll
    for (int ks = 0; ks < 4; ks++) {
        const uint32_t off = SWZ((uint32_t)((w*16 + lrow) * 128 + ks*32 + lkb));
        LDM4(qh[ks], QH + off);
    }

    const int nq0 = qt * 128 + w * 16 + r0;
    const int nq1 = nq0 + 8;
    const float polq0 = policy[b * N_ + nq0];
    const float polq1 = policy[b * N_ + nq1];
    const uint32_t pq0h = pack2h(polq0, polq0);
    const uint32_t pq1h = pack2h(polq1, polq1);

    float mb0 = 0.f, mb1 = 0.f;          // fixed base (set at kt==0)
    float pm0 = -1e30f, pm1 = -1e30f;    // running max in BIASED domain
    float lacc[4] = {};
    float O[8][4] = {};

    int sidx = 0;
    for (int kt = 0; kt < 8; kt++) {
        const uint32_t ST = ST0 + sidx * AST;
        const uint32_t* polKs = (const uint32_t*)(sbp + (PK0 - sb0) + sidx * 256);
        const bool diag  = (kt == qt);
        const bool first = (kt == 0);
        const float ib0 = first ? 0.f : -mb0;
        const float ib1 = first ? 0.f : -mb1;

        #pragma unroll
        for (int half = 0; half < 2; half++) {
            // ---- S - mb = Q K^T accumulated onto -mb init ----
            float Sf[8][4];
            #pragma unroll
            for (int nf = 0; nf < 8; nf++) {
                Sf[nf][0] = ib0; Sf[nf][1] = ib0;
                Sf[nf][2] = ib1; Sf[nf][3] = ib1;
            }
            #pragma unroll
            for (int ks = 0; ks < 4; ks++) {
                #pragma unroll
                for (int ng = 0; ng < 4; ng++) {
                    uint32_t kh4[4];
                    const int row = half*64 + ng*16 + lrow;
                    const uint32_t off = SWZ((uint32_t)(row * 128 + ks*32 + lkb));
                    LDM4(kh4, ST + off);
                    #pragma unroll
                    for (int hl = 0; hl < 2; hl++)
                        MMAH(Sf[2*ng+hl], qh[ks], kh4[hl], kh4[2+hl]);
                }
            }

            float t0 = -1e30f, t1 = -1e30f;
            #pragma unroll
            for (int nf = 0; nf < 8; nf++) {
                t0 = fmaxf(t0, fmaxf(Sf[nf][0], Sf[nf][1]));
                t1 = fmaxf(t1, fmaxf(Sf[nf][2], Sf[nf][3]));
            }
            if (first && half == 0) {
                float u0 = t0, u1 = t1;
                u0 = fmaxf(u0, __shfl_xor_sync(0xffffffffu, u0, 1));
                u0 = fmaxf(u0, __shfl_xor_sync(0xffffffffu, u0, 2));
                u1 = fmaxf(u1, __shfl_xor_sync(0xffffffffu, u1, 1));
                u1 = fmaxf(u1, __shfl_xor_sync(0xffffffffu, u1, 2));
                mb0 = u0; mb1 = u1;
            }
            // pm tracked in biased domain (kt0 values are raw -> subtract mb)
            pm0 = fmaxf(pm0, first ? (t0 - mb0) : t0);
            pm1 = fmaxf(pm1, first ? (t1 - mb1) : t1);

            uint32_t ph[4][4];
            if (diag) {
                // exact fp32 path on the diagonal tile
                const float a0 = first ? mb0 : 0.f;
                const float a1 = first ? mb1 : 0.f;
                #pragma unroll
                for (int nf = 0; nf < 8; nf++) {
                    const uint32_t pkbits = polKs[half*32 + nf*4 + (lane & 3)];
                    __half2 pkh = *reinterpret_cast<const __half2*>(&pkbits);
                    const float pk0 = __low2float(pkh), pk1 = __high2float(pkh);
                    float mk00 = polq0 * pk0, mk01 = polq0 * pk1;
                    float mk10 = polq1 * pk0, mk11 = polq1 * pk1;
                    const int col = kt * 128 + half*64 + nf * 8 + c2;
                    if (col     == nq0) mk00 = 1.f;
                    if (col + 1 == nq0) mk01 = 1.f;
                    if (col     == nq1) mk10 = 1.f;
                    if (col + 1 == nq1) mk11 = 1.f;
                    const float p00 = ex2(Sf[nf][0] - a0) * mk00;
                    const float p01 = ex2(Sf[nf][1] - a0) * mk01;
                    const float p10 = ex2(Sf[nf][2] - a1) * mk10;
                    const float p11 = ex2(Sf[nf][3] - a1) * mk11;
                    const int kc = nf >> 1, base = (nf & 1) * 2;
                    ph[kc][base]   = pack2h(p00, p01);
                    ph[kc][base+1] = pack2h(p10, p11);
                }
            } else if (first) {
                #pragma unroll
                for (int nf = 0; nf < 8; nf++) {
                    const uint32_t pk = polKs[half*32 + nf*4 + (lane & 3)];
                    const uint32_t a0 = pack2h(Sf[nf][0] - mb0, Sf[nf][1] - mb0);
                    const uint32_t a1 = pack2h(Sf[nf][2] - mb1, Sf[nf][3] - mb1);
                    const int kc = nf >> 1, base = (nf & 1) * 2;
                    ph[kc][base]   = hmul2(ex2h2(a0), hmul2(pq0h, pk));
                    ph[kc][base+1] = hmul2(ex2h2(a1), hmul2(pq1h, pk));
                }
            } else {
                // steady state: Sf already biased -> no subtraction
                #pragma unroll
                for (int nf = 0; nf < 8; nf++) {
                    const uint32_t pk = polKs[half*32 + nf*4 + (lane & 3)];
                    const uint32_t a0 = pack2h(Sf[nf][0], Sf[nf][1]);
                    const uint32_t a1 = pack2h(Sf[nf][2], Sf[nf][3]);
                    const int kc = nf >> 1, base = (nf & 1) * 2;
                    ph[kc][base]   = hmul2(ex2h2(a0), hmul2(pq0h, pk));
                    ph[kc][base+1] = hmul2(ex2h2(a1), hmul2(pq1h, pk));
                }
            }

            #pragma unroll
            for (int kc = 0; kc < 4; kc++) {
                MMAH(lacc, ph[kc], ONESH, ONESH);
                #pragma unroll
                for (int ng = 0; ng < 4; ng++) {
                    uint32_t vh4[4];
                    const int vrow = half*64 + kc*16 + lrow;
                    const uint32_t off = SWZ((uint32_t)(vrow * 128 + ng*32 + lkb));
                    LDM4T(vh4, ST + 16384 + off);
                    #pragma unroll
                    for (int hl = 0; hl < 2; hl++)
                        MMAH(O[2*ng+hl], ph[kc], vh4[2*hl], vh4[2*hl+1]);
                }
            }
        }

        __syncthreads();
        if (kt + 2 < 8) {
            const int kt2 = kt + 2;
            #pragma unroll
            for (int i = 0; i < 4; i++) {
                const int r = rb + 32 * i;
                const uint32_t d = SWZ((uint32_t)(r * 128 + g8 * 16));
                const size_t src = (bhN + kt2 * 128 + r) * HD + g8 * 8;
                cpa16(ST + 0*16384 + d, g_kh + src);
                cpa16(ST + 1*16384 + d, g_vh + src);
            }
            if (tid < 16) cpa16(PK0 + sidx * 256 + tid * 16,
                                g_polh + b * N_ + kt2 * 128 + tid * 8);
        }
        CP_COMMIT();
        if (kt + 1 < 8) { CP_WAIT1(); __syncthreads(); }
        sidx ^= 1;
    }

    // ---- epilogue: exact eps correction for the base shift ----
    pm0 = fmaxf(pm0, __shfl_xor_sync(0xffffffffu, pm0, 1));
    pm0 = fmaxf(pm0, __shfl_xor_sync(0xffffffffu, pm0, 2));
    pm1 = fmaxf(pm1, __shfl_xor_sync(0xffffffffu, pm1, 1));
    pm1 = fmaxf(pm1, __shfl_xor_sync(0xffffffffu, pm1, 2));
    const float c0 = ex2(pm0);
    const float c1 = ex2(pm1);
    const float e0 = EPSN * c0, e1 = EPSN * c1;
    const float inv0 = 1.f / (lacc[0] + EPS * c0);
    const float inv1 = 1.f / (lacc[2] + EPS * c1);
    #pragma unroll
    for (int nf = 0; nf < 8; nf++) {
        const int col = nf * 8 + c2;
        const float vs0 = g_vsum[bh * HD + col];
        const float vs1 = g_vsum[bh * HD + col + 1];
        const float o00 = (O[nf][0] + e0 * vs0) * inv0;
        const float o01 = (O[nf][1] + e0 * vs1) * inv0;
        const float o10 = (O[nf][2] + e1 * vs0) * inv1;
        const float o11 = (O[nf][3] + e1 * vs1) * inv1;
        const size_t i0 = (((size_t)(b * N_ + nq0)) * C_ + h * HD + col) >> 1;
        ((uint32_t*)g_ah)[i0] = pack2h(o00, o01);
        const size_t i1 = (((size_t)(b * N_ + nq1)) * C_ + h * HD + col) >> 1;
        ((uint32_t*)g_ah)[i1] = pack2h(o10, o11);
    }
}

// ---------------------------------------------------------------------------
extern "C" void kernel_launch(void* const* d_in, const int* in_sizes, int n_in,
                              void* d_out, int out_size) {
    const float* x      = (const float*)d_in[0];
    const float* policy = (const float*)d_in[1];
    const float* Wqkv   = (const float*)d_in[2];
    const float* Wproj  = (const float*)d_in[3];
    const float* bproj  = (const float*)d_in[4];
    float* out = (float*)d_out;

    __half *xh, *wqh, *wph, *ah;
    cudaGetSymbolAddress((void**)&xh,  g_xh);
    cudaGetSymbolAddress((void**)&wqh, g_wqh);
    cudaGetSymbolAddress((void**)&wph, g_wph);
    cudaGetSymbolAddress((void**)&ah,  g_ah);

    cudaFuncSetAttribute(mma_gemm_kernel,
                         cudaFuncAttributeMaxDynamicSharedMemorySize, 99328);
    cudaFuncSetAttribute(mma_gemm64_kernel,
                         cudaFuncAttributeMaxDynamicSharedMemorySize, 50176);
    cudaFuncSetAttribute(attn_mma_kernel,
                         cudaFuncAttributeMaxDynamicSharedMemorySize, 83968);

    const int qtotal = NX4 + NWQ4 + NWP4 + NP4;
    quant_all_kernel<<<(qtotal + 255)/256, 256>>>(x, Wqkv, Wproj, policy);

    mma_gemm_kernel<<<dim3(QKV_N/128, M_TOT/128), 256, 99328>>>(xh, wqh);

    vsum_kernel<<<B_*H_, 256>>>();

    attn_mma_kernel<<<dim3(8, 96), 256, 83968>>>(policy);

    mma_gemm64_kernel<<<dim3(C_/64, M_TOT/128), 256, 50176>>>(ah, wph, bproj, out);
}